// round 9
// baseline (speedup 1.0000x reference)
#include <cuda_runtime.h>
#include <cuda_bf16.h>
#include <cuda_fp16.h>
#include <cstdint>
#include <math.h>

#define B_      64
#define S_      4096
#define A_      4
#define L_      64
#define D_      300
#define AL_     256
#define KPAD_   320         // padded K for bf16 scratch
#define WINDOW_ 60
#define NW_     808
#define WPT_    32          // windows per warp task (pool)
#define NTASK_  26          // ceil(808/32)
#define ROWS_T_ 215         // 5*32 + 55 story rows per pool task
#define NKT_    10          // GEMM K tiles of 32
#define PITCH_  80          // smem row pitch bytes (conflict-free ldmatrix)

// 3-stage smem layout: stage = A(128x80) + B(256x80) = 30720 B
#define STG_SZ_   30720
#define OFF_SQA_  92160
#define OFF_SQB_  92672
#define SMEM_GEMM 93696

__device__ __half g_scores[(size_t)B_ * S_ * AL_];          // 134 MB fp16 scores
__device__ __nv_bfloat16 g_abf[(size_t)B_ * S_ * KPAD_];    // 167 MB bf16 A
__device__ __nv_bfloat16 g_bbf[(size_t)B_ * AL_ * KPAD_];   // 10.5 MB bf16 B
__device__ float g_inv_s[B_ * S_];
__device__ float g_inv_a[B_ * AL_];
__device__ float g_taskmax[B_ * A_ * NTASK_];

__device__ __forceinline__ uint32_t smem_u32(const void* p) {
    uint32_t a;
    asm("{ .reg .u64 t; cvta.to.shared.u64 t, %1; cvt.u32.u64 %0, t; }" : "=r"(a) : "l"(p));
    return a;
}
__device__ __forceinline__ uint32_t pk2(float lo, float hi) {
    uint32_t r;
    asm("cvt.rn.bf16x2.f32 %0, %1, %2;" : "=r"(r) : "f"(hi), "f"(lo));
    return r;
}
__device__ __forceinline__ void ldm4(uint32_t* r, uint32_t addr) {
    asm volatile("ldmatrix.sync.aligned.m8n8.x4.shared.b16 {%0,%1,%2,%3}, [%4];"
                 : "=r"(r[0]), "=r"(r[1]), "=r"(r[2]), "=r"(r[3]) : "r"(addr));
}
__device__ __forceinline__ void mma_bf16(float* d, const uint32_t* a, const uint32_t* b) {
    asm volatile("mma.sync.aligned.m16n8k16.row.col.f32.bf16.bf16.f32 "
                 "{%0,%1,%2,%3}, {%4,%5,%6,%7}, {%8,%9}, {%0,%1,%2,%3};"
                 : "+f"(d[0]), "+f"(d[1]), "+f"(d[2]), "+f"(d[3])
                 : "r"(a[0]), "r"(a[1]), "r"(a[2]), "r"(a[3]), "r"(b[0]), "r"(b[1]));
}
__device__ __forceinline__ void cp16(uint32_t dst, const void* src) {
    asm volatile("cp.async.ca.shared.global [%0], [%1], 16;" :: "r"(dst), "l"(src));
}
__device__ __forceinline__ uint32_t hmul2(uint32_t a, uint32_t b) {
    uint32_t r;
    asm("mul.f16x2 %0, %1, %2;" : "=r"(r) : "r"(a), "r"(b));
    return r;
}
__device__ __forceinline__ uint32_t hmax2(uint32_t a, uint32_t b) {
    uint32_t r;
    asm("max.f16x2 %0, %1, %2;" : "=r"(r) : "r"(a), "r"(b));
    return r;
}

// ---------------------------------------------------------------------------
// Convert BOTH inputs fp32 -> bf16 (zero-padded K=320) + exact fp32 inv norms.
// One warp per row; rows [0, B*S) = l_s, rows [B*S, B*S + B*AL) = l_a.
// ---------------------------------------------------------------------------
__global__ __launch_bounds__(256) void conv_kernel(const float* __restrict__ ls,
                                                   const float* __restrict__ la) {
    const int row = blockIdx.x * 8 + (threadIdx.x >> 5);
    const int lane = threadIdx.x & 31;
    const float2* src;
    uint32_t* dst;
    float* invp;
    if (row < B_ * S_) {
        src = (const float2*)(ls + (size_t)row * D_);
        dst = (uint32_t*)(g_abf + (size_t)row * KPAD_);
        invp = g_inv_s + row;
    } else {
        const int r2 = row - B_ * S_;
        src = (const float2*)(la + (size_t)r2 * D_);
        dst = (uint32_t*)(g_bbf + (size_t)r2 * KPAD_);
        invp = g_inv_a + r2;
    }
    float sq = 0.f;
#pragma unroll
    for (int i = 0; i < 5; i++) {
        const int idx = lane + 32 * i;            // pair index, 0..159
        float2 v = make_float2(0.f, 0.f);
        if (idx < 150) v = src[idx];              // 150 pairs = 300 floats
        sq += v.x * v.x + v.y * v.y;
        dst[idx] = pk2(v.x, v.y);
    }
#pragma unroll
    for (int o = 16; o; o >>= 1) sq += __shfl_xor_sync(0xffffffffu, sq, o);
    if (lane == 0) *invp = rsqrtf(sq + 1e-6f);
}

// ---------------------------------------------------------------------------
// GEMM: scores[b][s][al] = (A[s].B[al]) * inv_s * inv_a, fp16 out.
// CTA 128M x 256N, 8 warps (2M x 4N), warp tile 64x64, K-tile 32.
// Pure cp.async 3-stage pipeline; all operands bf16 from scratch.
// ---------------------------------------------------------------------------
__global__ __launch_bounds__(256) void gemm_kernel() {
    extern __shared__ __align__(128) char sm[];
    float* sqA_sh = (float*)(sm + OFF_SQA_);
    float* sqB_sh = (float*)(sm + OFF_SQB_);
    const uint32_t smb = smem_u32(sm);

    const int tid  = threadIdx.x;
    const int lane = tid & 31, warp = tid >> 5;
    const int b  = blockIdx.y;
    const int s0 = blockIdx.x * 128;
    const char* Aabf = (const char*)g_abf + ((size_t)b * S_ + s0) * (KPAD_ * 2);
    const char* Bbf  = (const char*)g_bbf + (size_t)b * AL_ * (KPAD_ * 2);

    const int wm = (warp & 1) * 64;
    const int wn = (warp >> 1) * 64;
    const int gid = lane >> 2, t4 = lane & 3;

    const int a_off0 = (wm + (lane & 15)) * PITCH_ + ((lane >> 4) << 4);
    const int grp = lane >> 3;
    const int b_offj = (wn + (lane & 7) + ((grp >> 1) << 3)) * PITCH_ + ((grp & 1) << 4);

    float acc[4][8][4];
#pragma unroll
    for (int mt = 0; mt < 4; mt++)
#pragma unroll
        for (int nt = 0; nt < 8; nt++)
#pragma unroll
            for (int i = 0; i < 4; i++) acc[mt][nt][i] = 0.f;

    auto issueTile = [&](int kt, int st) {
        const uint32_t abase = smb + st * STG_SZ_;
        const uint32_t bbase = abase + 10240;
        {   // A: thread -> row tid>>1, k-half tid&1 (2 x 16B)
            const uint32_t dst = abase + (tid >> 1) * PITCH_ + (tid & 1) * 32;
            const char* srcp = Aabf + (size_t)(tid >> 1) * (KPAD_ * 2)
                             + kt * 64 + (tid & 1) * 32;
            cp16(dst, srcp);
            cp16(dst + 16, srcp + 16);
        }
        {   // B: thread -> row tid (4 x 16B)
            const uint32_t dst = bbase + tid * PITCH_;
            const char* srcp = Bbf + (size_t)tid * (KPAD_ * 2) + kt * 64;
#pragma unroll
            for (int j = 0; j < 4; j++) cp16(dst + j * 16, srcp + j * 16);
        }
        asm volatile("cp.async.commit_group;");
    };

    // prologue: 3 stages in flight
    issueTile(0, 0);
    issueTile(1, 1);
    issueTile(2, 2);

    int st = 0;
#pragma unroll 1
    for (int kt = 0; kt < NKT_; ++kt) {
        if (kt <= NKT_ - 3)      asm volatile("cp.async.wait_group 2;");
        else if (kt == NKT_ - 2) asm volatile("cp.async.wait_group 1;");
        else                     asm volatile("cp.async.wait_group 0;");
        __syncthreads();                         // tile kt visible to all warps

        const uint32_t asb = smb + st * STG_SZ_;
        const uint32_t bsb = asb + 10240;
#pragma unroll
        for (int ks = 0; ks < 2; ks++) {
            uint32_t af[4][4];
#pragma unroll
            for (int mt = 0; mt < 4; mt++)
                ldm4(af[mt], asb + a_off0 + mt * 16 * PITCH_ + ks * 32);
            uint32_t bf[8][2];
#pragma unroll
            for (int j = 0; j < 4; j++) {
                uint32_t r[4];
                ldm4(r, bsb + b_offj + j * 16 * PITCH_ + ks * 32);
                bf[2*j][0] = r[0]; bf[2*j][1] = r[1];
                bf[2*j+1][0] = r[2]; bf[2*j+1][1] = r[3];
            }
#pragma unroll
            for (int nt = 0; nt < 8; nt++)
#pragma unroll
                for (int mt = 0; mt < 4; mt++)
                    mma_bf16(acc[mt][nt], af[mt], bf[nt]);
        }

        __syncthreads();                         // all warps done reading stage
        if (kt + 3 < NKT_) issueTile(kt + 3, st);
        st = (st == 2) ? 0 : st + 1;
    }

    // inverse norms precomputed by conv_kernel
    if (tid < 128) sqA_sh[tid] = g_inv_s[b * S_ + s0 + tid];
    sqB_sh[tid] = g_inv_a[b * AL_ + tid];
    __syncthreads();

    __half* out = g_scores + ((size_t)b * S_ + s0) * AL_;
#pragma unroll
    for (int mt = 0; mt < 4; mt++) {
#pragma unroll
        for (int hh = 0; hh < 2; hh++) {
            const int r = wm + mt * 16 + gid + hh * 8;
            const float is = sqA_sh[r];
#pragma unroll
            for (int nt = 0; nt < 8; nt++) {
                const int c = wn + nt * 8 + t4 * 2;
                const float vx = acc[mt][nt][hh * 2 + 0] * is * sqB_sh[c];
                const float vy = acc[mt][nt][hh * 2 + 1] * is * sqB_sh[c + 1];
                *(__half2*)(out + (size_t)r * AL_ + c) = __floats2half2_rn(vx, vy);
            }
        }
    }
}

// ---------------------------------------------------------------------------
// Pool: warp = 32 windows of one (b,a), fp16x2 math (R8 proven).
// ---------------------------------------------------------------------------
__global__ __launch_bounds__(256) void pool_kernel(const float* __restrict__ wg) {
    __shared__ uint32_t gs2[WINDOW_];
    const int tid = threadIdx.x;
    if (tid < WINDOW_) {
        const __half h = __float2half_rn(wg[tid]);
        gs2[tid] = (uint32_t)__half_as_ushort(h) * 0x10001u;
    }
    __syncthreads();

    const int lane = tid & 31;
    const int task = blockIdx.x * 8 + (tid >> 5);   // 832*8 = 6656 = 256*26
    const int ba = task / NTASK_;
    const int chunk = task - ba * NTASK_;
    const int nw0 = chunk * WPT_;
    const int sbase = 5 * nw0;
    const __half* src = g_scores + (size_t)(ba >> 2) * S_ * AL_
                      + (size_t)(ba & 3) * L_ + 2 * lane;

    uint32_t acc[WPT_];
#pragma unroll
    for (int i = 0; i < WPT_; ++i) acc[i] = 0xFC00FC00u;   // -inf | -inf

#pragma unroll 1
    for (int p = 0; p < 5; ++p) {
        uint32_t g12[12];
#pragma unroll
        for (int q = 0; q < 12; ++q) g12[q] = gs2[5 * q + p];
#pragma unroll
        for (int r = 0; r < 43; ++r) {
            const int so = 5 * r + p;
            const int s = sbase + so;
            uint32_t v = 0u;
            if (so < ROWS_T_ && s < S_) v = *(const uint32_t*)(src + (size_t)s * AL_);
#pragma unroll
            for (int q = 0; q < 12; ++q) {
                const int w = r - q;                 // compile-time
                if (w >= 0 && w < WPT_)
                    acc[w] = hmax2(acc[w], hmul2(g12[q], v));
            }
        }
    }

    float localmax = -INFINITY;
#pragma unroll
    for (int w = 0; w < WPT_; ++w) {
        const float2 f = __half22float2(*(__half2*)&acc[w]);
        float sum = f.x + f.y;
        float cnt = (f.x != 0.f ? 1.f : 0.f) + (f.y != 0.f ? 1.f : 0.f);
#pragma unroll
        for (int o = 16; o; o >>= 1) {
            sum += __shfl_xor_sync(0xffffffffu, sum, o);
            cnt += __shfl_xor_sync(0xffffffffu, cnt, o);
        }
        if (nw0 + w < NW_) localmax = fmaxf(localmax, sum / (cnt + 1e-5f));
    }
    if (lane == 0) g_taskmax[task] = localmax;
}

__global__ void final_kernel(const float* __restrict__ alpha, float* __restrict__ out) {
    const int i = threadIdx.x;  // 0..255 = b*4+a
    float mx = -INFINITY;
#pragma unroll
    for (int c = 0; c < NTASK_; ++c) mx = fmaxf(mx, g_taskmax[i * NTASK_ + c]);
    out[i] = mx * alpha[0];
}

// ---------------------------------------------------------------------------
extern "C" void kernel_launch(void* const* d_in, const int* in_sizes, int n_in,
                              void* d_out, int out_size) {
    const float* ls    = (const float*)d_in[0];
    const float* la    = (const float*)d_in[1];
    const float* alpha = (const float*)d_in[2];
    const float* wg    = (const float*)d_in[3];
    float* out = (float*)d_out;
    (void)in_sizes; (void)n_in; (void)out_size;

    conv_kernel<<<(B_ * S_ + B_ * AL_) / 8, 256>>>(ls, la);

    cudaFuncSetAttribute(gemm_kernel, cudaFuncAttributeMaxDynamicSharedMemorySize,
                         SMEM_GEMM);
    dim3 ggrid(S_ / 128, B_);   // (32, 64) -> 2048 CTAs
    gemm_kernel<<<ggrid, 256, SMEM_GEMM>>>();

    pool_kernel<<<(B_ * A_ * NTASK_) / 8, 256>>>(wg);

    final_kernel<<<1, 256>>>(alpha, out);
}